// round 3
// baseline (speedup 1.0000x reference)
#include <cuda_runtime.h>
#include <cuda_bf16.h>
#include <cstdint>
#include <cstddef>

#define DI 4096
#define DO 4096
#define MT 8192
#define RANK 8
#define LORA_SCALE 2.0f

// ---------------- scratch (device globals; no allocation allowed) ----------------
__device__ float g_A_eff[RANK * DI];            // fwht-folded A  (8 x 4096)
__device__ float g_B_eff[DO * RANK];            // fwht-folded B  (4096 x 8), row-major [o][r]
__device__ __nv_bfloat16 g_W_hi[(size_t)DO * DI];
__device__ __nv_bfloat16 g_W_lo[(size_t)DO * DI];
__device__ __nv_bfloat16 g_x_hi[(size_t)MT * DI];
__device__ __nv_bfloat16 g_x_lo[(size_t)MT * DI];

__device__ __forceinline__ uint32_t smem_u32(const void* p) {
    uint32_t a;
    asm("{ .reg .u64 t; cvta.to.shared.u64 t, %1; cvt.u32.u64 %0, t; }" : "=r"(a) : "l"(p));
    return a;
}

// ---------------- prep 1: fold SRHT + permutations into A_eff / B_eff ----------------
__global__ void prep_fwht_kernel(const float* __restrict__ Amat, const float* __restrict__ Bmat,
                                 const float* __restrict__ in_signs, const float* __restrict__ out_signs,
                                 const int* __restrict__ in_perm, const int* __restrict__ out_perm) {
    __shared__ float buf[DI];
    int bx = blockIdx.x;          // 0..7 -> A_eff rows, 8..15 -> B_eff cols
    int tid = threadIdx.x;        // 512 threads
    if (bx < RANK) {
        int r = bx;
        for (int j = tid; j < DI; j += 512) {
            int p = in_perm[j];
            buf[j] = in_signs[p] * Amat[r * DI + p];
        }
    } else {
        int r = bx - RANK;
        for (int j = tid; j < DO; j += 512) {
            int p = out_perm[j];
            buf[j] = out_signs[p] * Bmat[p * RANK + r];
        }
    }
    for (int h = 1; h < DI; h <<= 1) {
        __syncthreads();
        for (int t = tid; t < DI / 2; t += 512) {
            int i = ((t & ~(h - 1)) << 1) | (t & (h - 1));
            float u = buf[i], v = buf[i + h];
            buf[i] = u + v;
            buf[i + h] = u - v;
        }
    }
    __syncthreads();
    const float s = 1.0f / 64.0f;   // 1/sqrt(4096)
    if (bx < RANK) {
        int r = bx;
        for (int j = tid; j < DI; j += 512) g_A_eff[r * DI + j] = buf[j] * s;
    } else {
        int r = bx - RANK;
        for (int j = tid; j < DO; j += 512) g_B_eff[j * RANK + r] = buf[j] * s;
    }
}

// ---------------- prep 2: W_eff = W + SCALE * B_eff @ A_eff, split to bf16 hi/lo ----------------
__device__ __forceinline__ void split_store4(__nv_bfloat16* hp, __nv_bfloat16* lp, float4 w) {
    __nv_bfloat16 h0 = __float2bfloat16_rn(w.x);
    __nv_bfloat16 h1 = __float2bfloat16_rn(w.y);
    __nv_bfloat16 h2 = __float2bfloat16_rn(w.z);
    __nv_bfloat16 h3 = __float2bfloat16_rn(w.w);
    __nv_bfloat16 l0 = __float2bfloat16_rn(w.x - __bfloat162float(h0));
    __nv_bfloat16 l1 = __float2bfloat16_rn(w.y - __bfloat162float(h1));
    __nv_bfloat16 l2 = __float2bfloat16_rn(w.z - __bfloat162float(h2));
    __nv_bfloat16 l3 = __float2bfloat16_rn(w.w - __bfloat162float(h3));
    __nv_bfloat162* H = reinterpret_cast<__nv_bfloat162*>(hp);
    __nv_bfloat162* L = reinterpret_cast<__nv_bfloat162*>(lp);
    H[0] = __halves2bfloat162(h0, h1);
    H[1] = __halves2bfloat162(h2, h3);
    L[0] = __halves2bfloat162(l0, l1);
    L[1] = __halves2bfloat162(l2, l3);
}

__global__ void weff_split_kernel(const float* __restrict__ W) {
    int gid = blockIdx.x * blockDim.x + threadIdx.x;
    size_t base = (size_t)gid * 4;
    int o = (int)(base >> 12);
    int i = (int)(base & 4095);
    float4 w = *reinterpret_cast<const float4*>(W + base);
#pragma unroll
    for (int r = 0; r < RANK; r++) {
        float bv = LORA_SCALE * g_B_eff[o * RANK + r];
        float4 a = *reinterpret_cast<const float4*>(g_A_eff + r * DI + i);
        w.x += bv * a.x; w.y += bv * a.y; w.z += bv * a.z; w.w += bv * a.w;
    }
    split_store4(g_W_hi + base, g_W_lo + base, w);
}

__global__ void xsplit_kernel(const float* __restrict__ x) {
    int gid = blockIdx.x * blockDim.x + threadIdx.x;
    size_t base = (size_t)gid * 4;
    float4 w = *reinterpret_cast<const float4*>(x + base);
    split_store4(g_x_hi + base, g_x_lo + base, w);
}

// ---------------- main GEMM: out[8192,4096] = x @ W_eff^T + b (mma.sync HMMA path) ----------------
#define CTA_M 256
#define CTA_N 128
#define KC 32
#define NCHUNK (DI / KC)        // 128
#define STAGES 4
// stage layout (bytes): A_hi[256*64] A_lo[256*64] B_hi[128*64] B_lo[128*64]
#define SA_H 0
#define SA_L 16384
#define SB_H 32768
#define SB_L 40960
#define STAGE_BYTES 49152
#define SMEM_TOTAL (STAGES * STAGE_BYTES)   // 192 KB

// swizzled smem offset for row r (64B rows), 16B-chunk c (0..3)
__device__ __forceinline__ uint32_t swz(int r, int c) {
    return (uint32_t)(r * 64 + ((c ^ ((r >> 1) & 3)) << 4));
}

__device__ __forceinline__ void cp16(uint32_t dst, const void* src) {
    asm volatile("cp.async.cg.shared.global [%0], [%1], 16;" :: "r"(dst), "l"(src));
}

__device__ __forceinline__ void ldsm4(uint32_t addr, uint32_t* r) {
    asm volatile("ldmatrix.sync.aligned.m8n8.x4.shared.b16 {%0,%1,%2,%3}, [%4];"
                 : "=r"(r[0]), "=r"(r[1]), "=r"(r[2]), "=r"(r[3]) : "r"(addr));
}

__device__ __forceinline__ void mma16816(float* c, const uint32_t* a, uint32_t b0, uint32_t b1) {
    asm volatile(
        "mma.sync.aligned.m16n8k16.row.col.f32.bf16.bf16.f32 "
        "{%0,%1,%2,%3}, {%4,%5,%6,%7}, {%8,%9}, {%0,%1,%2,%3};"
        : "+f"(c[0]), "+f"(c[1]), "+f"(c[2]), "+f"(c[3])
        : "r"(a[0]), "r"(a[1]), "r"(a[2]), "r"(a[3]), "r"(b0), "r"(b1));
}

__device__ __forceinline__ void load_stage(uint32_t stage, int chunk, int m0, int n0, int tid) {
    int k0 = chunk * KC;
    const __nv_bfloat16* xh = g_x_hi + (size_t)m0 * DI + k0;
    const __nv_bfloat16* xl = g_x_lo + (size_t)m0 * DI + k0;
    const __nv_bfloat16* wh = g_W_hi + (size_t)n0 * DI + k0;
    const __nv_bfloat16* wl = g_W_lo + (size_t)n0 * DI + k0;
#pragma unroll
    for (int i = 0; i < 4; i++) {           // A: 256 rows x 4 chunks of 16B
        int idx = tid + i * 256;
        int r = idx >> 2, c = idx & 3;
        uint32_t so = swz(r, c);
        const char* off = (const char*)nullptr + ((size_t)r * DI + c * 8) * 2;
        cp16(stage + SA_H + so, (const char*)xh + (size_t)r * DI * 2 + c * 16);
        cp16(stage + SA_L + so, (const char*)xl + (size_t)r * DI * 2 + c * 16);
        (void)off;
    }
#pragma unroll
    for (int i = 0; i < 2; i++) {           // B: 128 rows x 4 chunks
        int idx = tid + i * 256;
        int r = idx >> 2, c = idx & 3;
        uint32_t so = swz(r, c);
        cp16(stage + SB_H + so, (const char*)wh + (size_t)r * DI * 2 + c * 16);
        cp16(stage + SB_L + so, (const char*)wl + (size_t)r * DI * 2 + c * 16);
    }
    asm volatile("cp.async.commit_group;" ::: "memory");
}

__device__ __forceinline__ void compute_stage(uint32_t stage, float (*acc)[8][4],
                                              int lane, int warp_m, int warp_n) {
#pragma unroll
    for (int kk = 0; kk < 2; kk++) {        // two k16 steps per KC=32 chunk
        uint32_t ah[4][4], al[4][4], bh[4][4], bl[4][4];
        int lane15 = lane & 15;
        int lanehi = lane >> 4;
        int ca = kk * 2 + lanehi;
        // A frags (hi then lo)
#pragma unroll
        for (int mt = 0; mt < 4; mt++) {
            int r = warp_m * 64 + mt * 16 + lane15;
            uint32_t so = swz(r, ca);
            ldsm4(stage + SA_H + so, ah[mt]);
        }
        // B frags (hi)
        int nb = warp_n * 64 + (lane & 7) + ((lane >> 4) << 3);
        int cb = kk * 2 + ((lane >> 3) & 1);
#pragma unroll
        for (int np = 0; np < 4; np++) {
            uint32_t so = swz(nb + np * 16, cb);
            ldsm4(stage + SB_H + so, bh[np]);
        }
        // pass 1: x_hi * W_hi
#pragma unroll
        for (int mt = 0; mt < 4; mt++)
#pragma unroll
            for (int nt = 0; nt < 8; nt++)
                mma16816(acc[mt][nt], ah[mt], bh[nt >> 1][(nt & 1) * 2], bh[nt >> 1][(nt & 1) * 2 + 1]);
        // B lo frags
#pragma unroll
        for (int np = 0; np < 4; np++) {
            uint32_t so = swz(nb + np * 16, cb);
            ldsm4(stage + SB_L + so, bl[np]);
        }
        // pass 2: x_hi * W_lo
#pragma unroll
        for (int mt = 0; mt < 4; mt++)
#pragma unroll
            for (int nt = 0; nt < 8; nt++)
                mma16816(acc[mt][nt], ah[mt], bl[nt >> 1][(nt & 1) * 2], bl[nt >> 1][(nt & 1) * 2 + 1]);
        // A lo frags
#pragma unroll
        for (int mt = 0; mt < 4; mt++) {
            int r = warp_m * 64 + mt * 16 + lane15;
            uint32_t so = swz(r, ca);
            ldsm4(stage + SA_L + so, al[mt]);
        }
        // pass 3: x_lo * W_hi
#pragma unroll
        for (int mt = 0; mt < 4; mt++)
#pragma unroll
            for (int nt = 0; nt < 8; nt++)
                mma16816(acc[mt][nt], al[mt], bh[nt >> 1][(nt & 1) * 2], bh[nt >> 1][(nt & 1) * 2 + 1]);
    }
}

__global__ void __launch_bounds__(256, 1)
gemm_kernel(const float* __restrict__ bias, float* __restrict__ out) {
    extern __shared__ char smem[];
    uint32_t sb = smem_u32(smem);
    int tid = threadIdx.x;
    int lane = tid & 31;
    int wid = tid >> 5;              // 8 warps: warp_m = wid>>1 (0..3), warp_n = wid&1 (0..1)
    int warp_m = wid >> 1;
    int warp_n = wid & 1;
    int n0 = blockIdx.x * CTA_N;
    int m0 = blockIdx.y * CTA_M;

    float acc[4][8][4];
#pragma unroll
    for (int a = 0; a < 4; a++)
#pragma unroll
        for (int b = 0; b < 8; b++)
#pragma unroll
            for (int c = 0; c < 4; c++) acc[a][b][c] = 0.0f;

    // prologue: prefetch 3 chunks
    load_stage(sb + 0 * STAGE_BYTES, 0, m0, n0, tid);
    load_stage(sb + 1 * STAGE_BYTES, 1, m0, n0, tid);
    load_stage(sb + 2 * STAGE_BYTES, 2, m0, n0, tid);

#pragma unroll 1
    for (int chunk = 0; chunk < NCHUNK; chunk++) {
        asm volatile("cp.async.wait_group %0;" :: "n"(2) : "memory");
        __syncthreads();
        if (chunk + 3 < NCHUNK) {
            load_stage(sb + ((chunk + 3) & 3) * STAGE_BYTES, chunk + 3, m0, n0, tid);
        } else {
            asm volatile("cp.async.commit_group;" ::: "memory");
        }
        compute_stage(sb + (chunk & 3) * STAGE_BYTES, acc, lane, warp_m, warp_n);
    }

    // epilogue: add bias, store fp32
    int g = lane >> 2, t = lane & 3;
    int col0 = n0 + warp_n * 64;
    float2 bv[8];
#pragma unroll
    for (int nt = 0; nt < 8; nt++)
        bv[nt] = *reinterpret_cast<const float2*>(bias + col0 + nt * 8 + t * 2);
#pragma unroll
    for (int mt = 0; mt < 4; mt++) {
        int r0 = m0 + warp_m * 64 + mt * 16 + g;
        float* p0 = out + (size_t)r0 * DO;
        float* p1 = out + (size_t)(r0 + 8) * DO;
#pragma unroll
        for (int nt = 0; nt < 8; nt++) {
            int c = col0 + nt * 8 + t * 2;
            float2 v0, v1;
            v0.x = acc[mt][nt][0] + bv[nt].x;
            v0.y = acc[mt][nt][1] + bv[nt].y;
            v1.x = acc[mt][nt][2] + bv[nt].x;
            v1.y = acc[mt][nt][3] + bv[nt].y;
            *reinterpret_cast<float2*>(p0 + c) = v0;
            *reinterpret_cast<float2*>(p1 + c) = v1;
        }
    }
}

// ---------------- launch ----------------
extern "C" void kernel_launch(void* const* d_in, const int* in_sizes, int n_in,
                              void* d_out, int out_size) {
    const float* x         = (const float*)d_in[0];
    const float* W         = (const float*)d_in[1];
    const float* b         = (const float*)d_in[2];
    const float* A         = (const float*)d_in[3];
    const float* Bm        = (const float*)d_in[4];
    const float* in_signs  = (const float*)d_in[5];
    const float* out_signs = (const float*)d_in[6];
    const int*   in_perm   = (const int*)d_in[7];
    const int*   out_perm  = (const int*)d_in[9];
    float* out = (float*)d_out;

    prep_fwht_kernel<<<16, 512>>>(A, Bm, in_signs, out_signs, in_perm, out_perm);
    weff_split_kernel<<<(DO * DI) / (4 * 256), 256>>>(W);
    xsplit_kernel<<<(MT * DI) / (4 * 256), 256>>>(x);

    static int smem_set = 0;
    if (!smem_set) {
        cudaFuncSetAttribute(gemm_kernel, cudaFuncAttributeMaxDynamicSharedMemorySize, SMEM_TOTAL);
        smem_set = 1;
    }
    gemm_kernel<<<dim3(DO / CTA_N, MT / CTA_M), 256, SMEM_TOTAL>>>(b, out);
}

// round 4
// speedup vs baseline: 1.6462x; 1.6462x over previous
#include <cuda_runtime.h>
#include <cuda_bf16.h>
#include <cuda_fp16.h>
#include <cstdint>
#include <cstddef>

#define DI 4096
#define DO 4096
#define MT 8192
#define RANK 8
#define LORA_SCALE 2.0f

// ---------------- scratch (device globals; no allocation allowed) ----------------
__device__ float g_A_eff[RANK * DI];            // fwht-folded A  (8 x 4096)
__device__ float g_B_eff[DO * RANK];            // fwht-folded B  (4096 x 8), row-major [o][r]
__device__ __half g_W_hi[(size_t)DO * DI];
__device__ __half g_W_lo[(size_t)DO * DI];
__device__ __half g_x_h [(size_t)MT * DI];

__device__ __forceinline__ uint32_t smem_u32(const void* p) {
    uint32_t a;
    asm("{ .reg .u64 t; cvta.to.shared.u64 t, %1; cvt.u32.u64 %0, t; }" : "=r"(a) : "l"(p));
    return a;
}

// ---------------- prep 1: fold SRHT + permutations into A_eff / B_eff ----------------
__global__ void prep_fwht_kernel(const float* __restrict__ Amat, const float* __restrict__ Bmat,
                                 const float* __restrict__ in_signs, const float* __restrict__ out_signs,
                                 const int* __restrict__ in_perm, const int* __restrict__ out_perm) {
    __shared__ float buf[DI];
    int bx = blockIdx.x;          // 0..7 -> A_eff rows, 8..15 -> B_eff cols
    int tid = threadIdx.x;        // 512 threads
    if (bx < RANK) {
        int r = bx;
        for (int j = tid; j < DI; j += 512) {
            int p = in_perm[j];
            buf[j] = in_signs[p] * Amat[r * DI + p];
        }
    } else {
        int r = bx - RANK;
        for (int j = tid; j < DO; j += 512) {
            int p = out_perm[j];
            buf[j] = out_signs[p] * Bmat[p * RANK + r];
        }
    }
    for (int h = 1; h < DI; h <<= 1) {
        __syncthreads();
        for (int t = tid; t < DI / 2; t += 512) {
            int i = ((t & ~(h - 1)) << 1) | (t & (h - 1));
            float u = buf[i], v = buf[i + h];
            buf[i] = u + v;
            buf[i + h] = u - v;
        }
    }
    __syncthreads();
    const float s = 1.0f / 64.0f;   // 1/sqrt(4096)
    if (bx < RANK) {
        int r = bx;
        for (int j = tid; j < DI; j += 512) g_A_eff[r * DI + j] = buf[j] * s;
    } else {
        int r = bx - RANK;
        for (int j = tid; j < DO; j += 512) g_B_eff[j * RANK + r] = buf[j] * s;
    }
}

// ---------------- prep 2: W_eff = W + SCALE * B_eff @ A_eff, split to fp16 hi/lo ----------------
__global__ void weff_split_kernel(const float* __restrict__ W) {
    int gid = blockIdx.x * blockDim.x + threadIdx.x;
    size_t base = (size_t)gid * 4;
    int o = (int)(base >> 12);
    int i = (int)(base & 4095);
    float4 w = *reinterpret_cast<const float4*>(W + base);
#pragma unroll
    for (int r = 0; r < RANK; r++) {
        float bv = LORA_SCALE * g_B_eff[o * RANK + r];
        float4 a = *reinterpret_cast<const float4*>(g_A_eff + r * DI + i);
        w.x += bv * a.x; w.y += bv * a.y; w.z += bv * a.z; w.w += bv * a.w;
    }
    __half h0 = __float2half_rn(w.x), h1 = __float2half_rn(w.y);
    __half h2 = __float2half_rn(w.z), h3 = __float2half_rn(w.w);
    __half l0 = __float2half_rn(w.x - __half2float(h0));
    __half l1 = __float2half_rn(w.y - __half2float(h1));
    __half l2 = __float2half_rn(w.z - __half2float(h2));
    __half l3 = __float2half_rn(w.w - __half2float(h3));
    __half2* H = reinterpret_cast<__half2*>(g_W_hi + base);
    __half2* L = reinterpret_cast<__half2*>(g_W_lo + base);
    H[0] = __halves2half2(h0, h1); H[1] = __halves2half2(h2, h3);
    L[0] = __halves2half2(l0, l1); L[1] = __halves2half2(l2, l3);
}

// ---------------- prep 3: x -> fp16 ----------------
__global__ void xcvt_kernel(const float* __restrict__ x) {
    int gid = blockIdx.x * blockDim.x + threadIdx.x;
    size_t base = (size_t)gid * 4;
    float4 w = *reinterpret_cast<const float4*>(x + base);
    __half2* H = reinterpret_cast<__half2*>(g_x_h + base);
    H[0] = __halves2half2(__float2half_rn(w.x), __float2half_rn(w.y));
    H[1] = __halves2half2(__float2half_rn(w.z), __float2half_rn(w.w));
}

// ---------------- main GEMM: out[8192,4096] = x @ W_eff^T + b ----------------
// fp16 2-product split: x_h*W_hi + x_h*W_lo, fp32 accumulators.
#define CTA_M 256
#define CTA_N 128
#define KC 64                   // fp16 elems per K chunk = 128B per row
#define NCHUNK (DI / KC)        // 64
#define STAGES 3
// stage layout (bytes): A[256*128] B_hi[128*128] B_lo[128*128]
#define SA   0
#define SB_H 32768
#define SB_L 49152
#define STAGE_BYTES 65536
#define SMEM_TOTAL (STAGES * STAGE_BYTES)   // 192 KB

// swizzled smem offset for row r (128B rows), 16B-chunk c (0..7)
__device__ __forceinline__ uint32_t swz(int r, int c) {
    return (uint32_t)(r * 128 + ((c ^ (r & 7)) << 4));
}

__device__ __forceinline__ void cp16(uint32_t dst, const void* src) {
    asm volatile("cp.async.cg.shared.global [%0], [%1], 16;" :: "r"(dst), "l"(src));
}

__device__ __forceinline__ void ldsm4(uint32_t addr, uint32_t* r) {
    asm volatile("ldmatrix.sync.aligned.m8n8.x4.shared.b16 {%0,%1,%2,%3}, [%4];"
                 : "=r"(r[0]), "=r"(r[1]), "=r"(r[2]), "=r"(r[3]) : "r"(addr));
}

__device__ __forceinline__ void mma16816(float* c, const uint32_t* a, uint32_t b0, uint32_t b1) {
    asm volatile(
        "mma.sync.aligned.m16n8k16.row.col.f32.f16.f16.f32 "
        "{%0,%1,%2,%3}, {%4,%5,%6,%7}, {%8,%9}, {%0,%1,%2,%3};"
        : "+f"(c[0]), "+f"(c[1]), "+f"(c[2]), "+f"(c[3])
        : "r"(a[0]), "r"(a[1]), "r"(a[2]), "r"(a[3]), "r"(b0), "r"(b1));
}

__device__ __forceinline__ void load_stage(uint32_t stage, int chunk, int m0, int n0, int tid) {
    int k0 = chunk * KC;
    const char* xh = (const char*)(g_x_h  + (size_t)m0 * DI + k0);
    const char* wh = (const char*)(g_W_hi + (size_t)n0 * DI + k0);
    const char* wl = (const char*)(g_W_lo + (size_t)n0 * DI + k0);
#pragma unroll
    for (int i = 0; i < 4; i++) {           // A: 256 rows x 8 chunks of 16B
        int idx = tid + i * 512;
        int r = idx >> 3, c = idx & 7;
        cp16(stage + SA + swz(r, c), xh + (size_t)r * (DI * 2) + c * 16);
    }
#pragma unroll
    for (int i = 0; i < 2; i++) {           // B: 128 rows x 8 chunks, hi + lo
        int idx = tid + i * 512;
        int r = idx >> 3, c = idx & 7;
        uint32_t so = swz(r, c);
        size_t go = (size_t)r * (DI * 2) + c * 16;
        cp16(stage + SB_H + so, wh + go);
        cp16(stage + SB_L + so, wl + go);
    }
    asm volatile("cp.async.commit_group;" ::: "memory");
}

__device__ __forceinline__ void compute_stage(uint32_t stage, float (*acc)[4][4],
                                              int lane, int warp_m, int warp_n) {
    int lane15 = lane & 15;
    int lanehi = lane >> 4;
    int nb = warp_n * 32 + (lane & 7) + ((lane >> 4) << 3);
    int cbo = (lane >> 3) & 1;
#pragma unroll
    for (int kk = 0; kk < 4; kk++) {        // four k16 steps per KC=64 chunk
        uint32_t ah[4][4], bh[2][4], bl[2][4];
        int ca = kk * 2 + lanehi;
        int cb = kk * 2 + cbo;
#pragma unroll
        for (int mt = 0; mt < 4; mt++) {
            int r = warp_m * 64 + mt * 16 + lane15;
            ldsm4(stage + SA + swz(r, ca), ah[mt]);
        }
#pragma unroll
        for (int np = 0; np < 2; np++)
            ldsm4(stage + SB_H + swz(nb + np * 16, cb), bh[np]);
        // pass 1: x_h * W_hi
#pragma unroll
        for (int mt = 0; mt < 4; mt++)
#pragma unroll
            for (int nt = 0; nt < 4; nt++)
                mma16816(acc[mt][nt], ah[mt], bh[nt >> 1][(nt & 1) * 2], bh[nt >> 1][(nt & 1) * 2 + 1]);
#pragma unroll
        for (int np = 0; np < 2; np++)
            ldsm4(stage + SB_L + swz(nb + np * 16, cb), bl[np]);
        // pass 2: x_h * W_lo
#pragma unroll
        for (int mt = 0; mt < 4; mt++)
#pragma unroll
            for (int nt = 0; nt < 4; nt++)
                mma16816(acc[mt][nt], ah[mt], bl[nt >> 1][(nt & 1) * 2], bl[nt >> 1][(nt & 1) * 2 + 1]);
    }
}

__global__ void __launch_bounds__(512, 1)
gemm_kernel(const float* __restrict__ bias, float* __restrict__ out) {
    extern __shared__ char smem[];
    uint32_t sb = smem_u32(smem);
    int tid = threadIdx.x;
    int lane = tid & 31;
    int wid = tid >> 5;              // 16 warps: warp_m = wid>>2 (0..3), warp_n = wid&3 (0..3)
    int warp_m = wid >> 2;
    int warp_n = wid & 3;
    int n0 = blockIdx.x * CTA_N;
    int m0 = blockIdx.y * CTA_M;

    float acc[4][4][4];
#pragma unroll
    for (int a = 0; a < 4; a++)
#pragma unroll
        for (int b = 0; b < 4; b++)
#pragma unroll
            for (int c = 0; c < 4; c++) acc[a][b][c] = 0.0f;

    // prologue: prefetch 2 chunks
    load_stage(sb + 0 * STAGE_BYTES, 0, m0, n0, tid);
    load_stage(sb + 1 * STAGE_BYTES, 1, m0, n0, tid);

    int sc = 0;                       // compute stage index
    int sl = 2;                       // load stage index
#pragma unroll 1
    for (int chunk = 0; chunk < NCHUNK; chunk++) {
        asm volatile("cp.async.wait_group %0;" :: "n"(1) : "memory");
        __syncthreads();
        if (chunk + 2 < NCHUNK) {
            load_stage(sb + sl * STAGE_BYTES, chunk + 2, m0, n0, tid);
        } else {
            asm volatile("cp.async.commit_group;" ::: "memory");
        }
        compute_stage(sb + sc * STAGE_BYTES, acc, lane, warp_m, warp_n);
        sc = (sc == STAGES - 1) ? 0 : sc + 1;
        sl = (sl == STAGES - 1) ? 0 : sl + 1;
    }

    // epilogue: add bias, store fp32
    int g = lane >> 2, t = lane & 3;
    int col0 = n0 + warp_n * 32;
    float2 bv[4];
#pragma unroll
    for (int nt = 0; nt < 4; nt++)
        bv[nt] = *reinterpret_cast<const float2*>(bias + col0 + nt * 8 + t * 2);
#pragma unroll
    for (int mt = 0; mt < 4; mt++) {
        int r0 = m0 + warp_m * 64 + mt * 16 + g;
        float* p0 = out + (size_t)r0 * DO;
        float* p1 = out + (size_t)(r0 + 8) * DO;
#pragma unroll
        for (int nt = 0; nt < 4; nt++) {
            int c = col0 + nt * 8 + t * 2;
            float2 v0, v1;
            v0.x = acc[mt][nt][0] + bv[nt].x;
            v0.y = acc[mt][nt][1] + bv[nt].y;
            v1.x = acc[mt][nt][2] + bv[nt].x;
            v1.y = acc[mt][nt][3] + bv[nt].y;
            *reinterpret_cast<float2*>(p0 + c) = v0;
            *reinterpret_cast<float2*>(p1 + c) = v1;
        }
    }
}

// ---------------- launch ----------------
extern "C" void kernel_launch(void* const* d_in, const int* in_sizes, int n_in,
                              void* d_out, int out_size) {
    const float* x         = (const float*)d_in[0];
    const float* W         = (const float*)d_in[1];
    const float* b         = (const float*)d_in[2];
    const float* A         = (const float*)d_in[3];
    const float* Bm        = (const float*)d_in[4];
    const float* in_signs  = (const float*)d_in[5];
    const float* out_signs = (const float*)d_in[6];
    const int*   in_perm   = (const int*)d_in[7];
    const int*   out_perm  = (const int*)d_in[9];
    float* out = (float*)d_out;

    prep_fwht_kernel<<<16, 512>>>(A, Bm, in_signs, out_signs, in_perm, out_perm);
    weff_split_kernel<<<(DO * DI) / (4 * 256), 256>>>(W);
    xcvt_kernel<<<(MT * DI) / (4 * 256), 256>>>(x);

    static int smem_set = 0;
    if (!smem_set) {
        cudaFuncSetAttribute(gemm_kernel, cudaFuncAttributeMaxDynamicSharedMemorySize, SMEM_TOTAL);
        smem_set = 1;
    }
    gemm_kernel<<<dim3(DO / CTA_N, MT / CTA_M), 512, SMEM_TOTAL>>>(b, out);
}

// round 5
// speedup vs baseline: 2.7965x; 1.6988x over previous
#include <cuda_runtime.h>
#include <cuda_bf16.h>
#include <cuda_fp16.h>
#include <cstdint>
#include <cstddef>

#define DI 4096
#define DO 4096
#define MT 8192
#define RANK 8
#define LORA_SCALE 2.0f

// ---------------- scratch (device globals; no allocation allowed) ----------------
__device__ float g_A_eff[RANK * DI];            // fwht-folded A  (8 x 4096)
__device__ float g_B_eff[DO * RANK];            // fwht-folded B  (4096 x 8), row-major [o][r]
__device__ __half g_W_h[(size_t)DO * DI];
__device__ __half g_x_h[(size_t)MT * DI];

__device__ __forceinline__ uint32_t smem_u32(const void* p) {
    uint32_t a;
    asm("{ .reg .u64 t; cvta.to.shared.u64 t, %1; cvt.u32.u64 %0, t; }" : "=r"(a) : "l"(p));
    return a;
}

// ---------------- prep 1: fold SRHT + permutations into A_eff / B_eff ----------------
__global__ void prep_fwht_kernel(const float* __restrict__ Amat, const float* __restrict__ Bmat,
                                 const float* __restrict__ in_signs, const float* __restrict__ out_signs,
                                 const int* __restrict__ in_perm, const int* __restrict__ out_perm) {
    __shared__ float buf[DI];
    int bx = blockIdx.x;          // 0..7 -> A_eff rows, 8..15 -> B_eff cols
    int tid = threadIdx.x;        // 512 threads
    if (bx < RANK) {
        int r = bx;
        for (int j = tid; j < DI; j += 512) {
            int p = in_perm[j];
            buf[j] = in_signs[p] * Amat[r * DI + p];
        }
    } else {
        int r = bx - RANK;
        for (int j = tid; j < DO; j += 512) {
            int p = out_perm[j];
            buf[j] = out_signs[p] * Bmat[p * RANK + r];
        }
    }
    for (int h = 1; h < DI; h <<= 1) {
        __syncthreads();
        for (int t = tid; t < DI / 2; t += 512) {
            int i = ((t & ~(h - 1)) << 1) | (t & (h - 1));
            float u = buf[i], v = buf[i + h];
            buf[i] = u + v;
            buf[i + h] = u - v;
        }
    }
    __syncthreads();
    const float s = 1.0f / 64.0f;   // 1/sqrt(4096)
    if (bx < RANK) {
        int r = bx;
        for (int j = tid; j < DI; j += 512) g_A_eff[r * DI + j] = buf[j] * s;
    } else {
        int r = bx - RANK;
        for (int j = tid; j < DO; j += 512) g_B_eff[j * RANK + r] = buf[j] * s;
    }
}

// ---------------- prep 2: W_eff = W + SCALE * B_eff @ A_eff -> fp16 ----------------
__global__ void weff_kernel(const float* __restrict__ W) {
    int gid = blockIdx.x * blockDim.x + threadIdx.x;
    size_t base = (size_t)gid * 4;
    int o = (int)(base >> 12);
    int i = (int)(base & 4095);
    float4 w = *reinterpret_cast<const float4*>(W + base);
#pragma unroll
    for (int r = 0; r < RANK; r++) {
        float bv = LORA_SCALE * g_B_eff[o * RANK + r];
        float4 a = *reinterpret_cast<const float4*>(g_A_eff + r * DI + i);
        w.x += bv * a.x; w.y += bv * a.y; w.z += bv * a.z; w.w += bv * a.w;
    }
    __half2* H = reinterpret_cast<__half2*>(g_W_h + base);
    H[0] = __halves2half2(__float2half_rn(w.x), __float2half_rn(w.y));
    H[1] = __halves2half2(__float2half_rn(w.z), __float2half_rn(w.w));
}

// ---------------- prep 3: x -> fp16 ----------------
__global__ void xcvt_kernel(const float* __restrict__ x) {
    int gid = blockIdx.x * blockDim.x + threadIdx.x;
    size_t base = (size_t)gid * 4;
    float4 w = *reinterpret_cast<const float4*>(x + base);
    __half2* H = reinterpret_cast<__half2*>(g_x_h + base);
    H[0] = __halves2half2(__float2half_rn(w.x), __float2half_rn(w.y));
    H[1] = __halves2half2(__float2half_rn(w.z), __float2half_rn(w.w));
}

// ---------------- main GEMM: out[8192,4096] = x @ W_eff^T + b (single fp16 product) ----------------
#define CTA_M 256
#define CTA_N 128
#define KC 64                   // fp16 elems per K chunk = 128B per row
#define NCHUNK (DI / KC)        // 64
#define STAGES 4
// stage layout (bytes): A[256*128] B[128*128]
#define SA 0
#define SB 32768
#define STAGE_BYTES 49152
#define SMEM_TOTAL (STAGES * STAGE_BYTES)   // 192 KB

// swizzled smem offset for row r (128B rows), 16B-chunk c (0..7)
__device__ __forceinline__ uint32_t swz(int r, int c) {
    return (uint32_t)(r * 128 + ((c ^ (r & 7)) << 4));
}

__device__ __forceinline__ void cp16(uint32_t dst, const void* src) {
    asm volatile("cp.async.cg.shared.global [%0], [%1], 16;" :: "r"(dst), "l"(src));
}

__device__ __forceinline__ void ldsm4(uint32_t addr, uint32_t* r) {
    asm volatile("ldmatrix.sync.aligned.m8n8.x4.shared.b16 {%0,%1,%2,%3}, [%4];"
                 : "=r"(r[0]), "=r"(r[1]), "=r"(r[2]), "=r"(r[3]) : "r"(addr));
}

__device__ __forceinline__ void mma16816(float* c, const uint32_t* a, uint32_t b0, uint32_t b1) {
    asm volatile(
        "mma.sync.aligned.m16n8k16.row.col.f32.f16.f16.f32 "
        "{%0,%1,%2,%3}, {%4,%5,%6,%7}, {%8,%9}, {%0,%1,%2,%3};"
        : "+f"(c[0]), "+f"(c[1]), "+f"(c[2]), "+f"(c[3])
        : "r"(a[0]), "r"(a[1]), "r"(a[2]), "r"(a[3]), "r"(b0), "r"(b1));
}

__device__ __forceinline__ void load_stage(uint32_t stage, int chunk, int m0, int n0, int tid) {
    int k0 = chunk * KC;
    const char* xh = (const char*)(g_x_h + (size_t)m0 * DI + k0);
    const char* wh = (const char*)(g_W_h + (size_t)n0 * DI + k0);
#pragma unroll
    for (int i = 0; i < 8; i++) {           // A: 256 rows x 8 chunks of 16B
        int idx = tid + i * 256;
        int r = idx >> 3, c = idx & 7;
        cp16(stage + SA + swz(r, c), xh + (size_t)r * (DI * 2) + c * 16);
    }
#pragma unroll
    for (int i = 0; i < 4; i++) {           // B: 128 rows x 8 chunks
        int idx = tid + i * 256;
        int r = idx >> 3, c = idx & 7;
        cp16(stage + SB + swz(r, c), wh + (size_t)r * (DI * 2) + c * 16);
    }
    asm volatile("cp.async.commit_group;" ::: "memory");
}

struct Frags {
    uint32_t a[4][4];
    uint32_t b[4][4];
};

__device__ __forceinline__ void load_frags(uint32_t stage, int kk, Frags& f,
                                           int lane, int warp_m, int warp_n) {
    int lane15 = lane & 15;
    int lanehi = lane >> 4;
    int ca = kk * 2 + lanehi;
#pragma unroll
    for (int mt = 0; mt < 4; mt++) {
        int r = warp_m * 64 + mt * 16 + lane15;
        ldsm4(stage + SA + swz(r, ca), f.a[mt]);
    }
    int nb = warp_n * 64 + (lane & 7) + ((lane >> 4) << 3);
    int cb = kk * 2 + ((lane >> 3) & 1);
#pragma unroll
    for (int np = 0; np < 4; np++)
        ldsm4(stage + SB + swz(nb + np * 16, cb), f.b[np]);
}

__device__ __forceinline__ void mma_frags(const Frags& f, float (*acc)[8][4]) {
#pragma unroll
    for (int mt = 0; mt < 4; mt++)
#pragma unroll
        for (int nt = 0; nt < 8; nt++)
            mma16816(acc[mt][nt], f.a[mt],
                     f.b[nt >> 1][(nt & 1) * 2], f.b[nt >> 1][(nt & 1) * 2 + 1]);
}

__global__ void __launch_bounds__(256, 1)
gemm_kernel(const float* __restrict__ bias, float* __restrict__ out) {
    extern __shared__ char smem[];
    uint32_t sb = smem_u32(smem);
    int tid = threadIdx.x;
    int lane = tid & 31;
    int wid = tid >> 5;              // 8 warps: warp_m = wid>>1 (0..3), warp_n = wid&1 (0..1)
    int warp_m = wid >> 1;
    int warp_n = wid & 1;
    int n0 = blockIdx.x * CTA_N;
    int m0 = blockIdx.y * CTA_M;

    float acc[4][8][4];
#pragma unroll
    for (int a = 0; a < 4; a++)
#pragma unroll
        for (int b = 0; b < 8; b++)
#pragma unroll
            for (int c = 0; c < 4; c++) acc[a][b][c] = 0.0f;

    // prologue: prefetch 3 chunks
    load_stage(sb + 0 * STAGE_BYTES, 0, m0, n0, tid);
    load_stage(sb + 1 * STAGE_BYTES, 1, m0, n0, tid);
    load_stage(sb + 2 * STAGE_BYTES, 2, m0, n0, tid);

    Frags fr[2];
#pragma unroll 1
    for (int chunk = 0; chunk < NCHUNK; chunk++) {
        asm volatile("cp.async.wait_group %0;" :: "n"(2) : "memory");
        __syncthreads();
        uint32_t stage = sb + (chunk & 3) * STAGE_BYTES;
        load_frags(stage, 0, fr[0], lane, warp_m, warp_n);
        if (chunk + 3 < NCHUNK) {
            load_stage(sb + ((chunk + 3) & 3) * STAGE_BYTES, chunk + 3, m0, n0, tid);
        } else {
            asm volatile("cp.async.commit_group;" ::: "memory");
        }
#pragma unroll
        for (int kk = 0; kk < 4; kk++) {
            if (kk < 3) load_frags(stage, kk + 1, fr[(kk + 1) & 1], lane, warp_m, warp_n);
            mma_frags(fr[kk & 1], acc);
        }
    }

    // epilogue: add bias, store fp32
    int g = lane >> 2, t = lane & 3;
    int col0 = n0 + warp_n * 64;
    float2 bv[8];
#pragma unroll
    for (int nt = 0; nt < 8; nt++)
        bv[nt] = *reinterpret_cast<const float2*>(bias + col0 + nt * 8 + t * 2);
#pragma unroll
    for (int mt = 0; mt < 4; mt++) {
        int r0 = m0 + warp_m * 64 + mt * 16 + g;
        float* p0 = out + (size_t)r0 * DO;
        float* p1 = out + (size_t)(r0 + 8) * DO;
#pragma unroll
        for (int nt = 0; nt < 8; nt++) {
            int c = col0 + nt * 8 + t * 2;
            float2 v0, v1;
            v0.x = acc[mt][nt][0] + bv[nt].x;
            v0.y = acc[mt][nt][1] + bv[nt].y;
            v1.x = acc[mt][nt][2] + bv[nt].x;
            v1.y = acc[mt][nt][3] + bv[nt].y;
            *reinterpret_cast<float2*>(p0 + c) = v0;
            *reinterpret_cast<float2*>(p1 + c) = v1;
        }
    }
}

// ---------------- launch ----------------
extern "C" void kernel_launch(void* const* d_in, const int* in_sizes, int n_in,
                              void* d_out, int out_size) {
    const float* x         = (const float*)d_in[0];
    const float* W         = (const float*)d_in[1];
    const float* b         = (const float*)d_in[2];
    const float* A         = (const float*)d_in[3];
    const float* Bm        = (const float*)d_in[4];
    const float* in_signs  = (const float*)d_in[5];
    const float* out_signs = (const float*)d_in[6];
    const int*   in_perm   = (const int*)d_in[7];
    const int*   out_perm  = (const int*)d_in[9];
    float* out = (float*)d_out;

    prep_fwht_kernel<<<16, 512>>>(A, Bm, in_signs, out_signs, in_perm, out_perm);
    weff_kernel<<<(DO * DI) / (4 * 256), 256>>>(W);
    xcvt_kernel<<<(MT * DI) / (4 * 256), 256>>>(x);

    static int smem_set = 0;
    if (!smem_set) {
        cudaFuncSetAttribute(gemm_kernel, cudaFuncAttributeMaxDynamicSharedMemorySize, SMEM_TOTAL);
        smem_set = 1;
    }
    gemm_kernel<<<dim3(DO / CTA_N, MT / CTA_M), 256, SMEM_TOTAL>>>(b, out);
}